// round 5
// baseline (speedup 1.0000x reference)
#include <cuda_runtime.h>
#include <cstddef>

// Problem constants
#define Bv 64
#define Nv 2048
#define Ev 16384
#define Fv 32
#define Hv 64
#define Kv 8
#define Cv 16
#define Gv 64
#define CKv 128          // C*K
#define NGv 131072       // N*G
#define CAPE 64          // max nodes per edge (mean 8)
#define CAPN 192         // max edges per node (mean 64)
#define CAPNP (CAPN + 8) // padded edge list (prefetch overrun guard)

typedef unsigned long long u64;

__device__ __forceinline__ u64 pack2(float lo, float hi) {
    u64 r; asm("mov.b64 %0,{%1,%2};" : "=l"(r) : "f"(lo), "f"(hi)); return r;
}
__device__ __forceinline__ void ffma2(u64& d, u64 a, u64 b) {
    asm("fma.rn.f32x2 %0,%1,%2,%0;" : "+l"(d) : "l"(a), "l"(b));
}
__device__ __forceinline__ float hsum2(u64 v) {
    float lo, hi; asm("mov.b64 {%0,%1},%2;" : "=f"(lo), "=f"(hi) : "l"(v));
    return lo + hi;
}

// ---------------- scratch (device globals; no allocation) ----------------
__device__ float g_w[Ev * Kv];                 // per-edge kernel weights [E,K]
__device__ int   g_ecnt[Ev];
__device__ int   g_enodes[Ev * CAPE];          // rinc CSR: nodes per edge
__device__ int   g_ncnt[Nv];
__device__ int   g_nedges[Nv * CAPN];          // linc CSR: edges per node
__device__ float g_z[(size_t)Ev * Bv * Cv];    // z in (E,B,C) layout, 67MB
__device__ u64   g_y[(size_t)Nv * Bv * 64];    // y pairs [n][b][64 u64], 67MB

// ---------------- K0: edge MLP -> w[E,K] ----------------
__global__ void k0_edgew(const float* __restrict__ ef,
                         const float* __restrict__ w1, const float* __restrict__ b1,
                         const float* __restrict__ w2, const float* __restrict__ b2) {
    __shared__ float w1s[Hv * Fv];
    __shared__ float w2s[Kv * Hv];
    __shared__ float b1s[Hv];
    __shared__ float b2s[Kv];
    int t = threadIdx.x;
    for (int i = t; i < Hv * Fv; i += 128) w1s[i] = w1[i];
    for (int i = t; i < Kv * Hv; i += 128) w2s[i] = w2[i];
    if (t < Hv) b1s[t] = b1[t];
    if (t < Kv) b2s[t] = b2[t];
    __syncthreads();

    int e = blockIdx.x * 128 + t;
    float efr[Fv];
#pragma unroll
    for (int q = 0; q < Fv / 4; ++q)
        ((float4*)efr)[q] = ((const float4*)(ef + (size_t)e * Fv))[q];
    float wk[Kv];
#pragma unroll
    for (int k = 0; k < Kv; ++k) wk[k] = b2s[k];
    for (int j = 0; j < Hv; ++j) {
        float s = b1s[j];
#pragma unroll
        for (int f = 0; f < Fv; ++f) s += efr[f] * w1s[j * Fv + f];
        s = fmaxf(s, 0.0f);
#pragma unroll
        for (int k = 0; k < Kv; ++k) wk[k] += s * w2s[k * Hv + j];
    }
#pragma unroll
    for (int k = 0; k < Kv; ++k) g_w[e * Kv + k] = wk[k];
}

// ---------------- ordered sparse row scan (deterministic compaction) ---------
template <int COLS, int CAP, int UNROLL>
__device__ __forceinline__ void scan_row(const float* __restrict__ row,
                                         int* __restrict__ outp,
                                         int* __restrict__ cntp, int lane) {
    int cnt = 0;
    const float4* r4 = (const float4*)row;
    const unsigned lt = (1u << lane) - 1u;
    for (int g = 0; g < COLS / 128; g += UNROLL) {
        float4 v[UNROLL];
#pragma unroll
        for (int u = 0; u < UNROLL; ++u) v[u] = r4[(size_t)(g + u) * 32 + lane];
#pragma unroll
        for (int u = 0; u < UNROLL; ++u) {
            float a0 = v[u].x, a1 = v[u].y, a2 = v[u].z, a3 = v[u].w;
            unsigned m0 = __ballot_sync(0xffffffffu, a0 != 0.0f);
            unsigned m1 = __ballot_sync(0xffffffffu, a1 != 0.0f);
            unsigned m2 = __ballot_sync(0xffffffffu, a2 != 0.0f);
            unsigned m3 = __ballot_sync(0xffffffffu, a3 != 0.0f);
            int prefix = __popc(m0 & lt) + __popc(m1 & lt) + __popc(m2 & lt) + __popc(m3 & lt);
            int base = (g + u) * 128 + lane * 4;
            int own = 0;
            if (a0 != 0.0f) { int p = cnt + prefix + own; if (p < CAP) outp[p] = base + 0; own++; }
            if (a1 != 0.0f) { int p = cnt + prefix + own; if (p < CAP) outp[p] = base + 1; own++; }
            if (a2 != 0.0f) { int p = cnt + prefix + own; if (p < CAP) outp[p] = base + 2; own++; }
            if (a3 != 0.0f) { int p = cnt + prefix + own; if (p < CAP) outp[p] = base + 3; own++; }
            cnt += __popc(m0) + __popc(m1) + __popc(m2) + __popc(m3);
        }
    }
    if (lane == 0) *cntp = (cnt < CAP) ? cnt : CAP;
}

// K1: rinc (E,N) -> per-edge node lists
__global__ void k1_scan_rinc(const float* __restrict__ rinc) {
    int w = (blockIdx.x * blockDim.x + threadIdx.x) >> 5;
    int lane = threadIdx.x & 31;
    scan_row<Nv, CAPE, 4>(rinc + (size_t)w * Nv, g_enodes + (size_t)w * CAPE, g_ecnt + w, lane);
}

// K2: linc (N,E) -> per-node edge lists (UNROLL 8 -> MLP 8; only 2048 warps)
__global__ void k2_scan_linc(const float* __restrict__ linc) {
    int w = (blockIdx.x * blockDim.x + threadIdx.x) >> 5;
    int lane = threadIdx.x & 31;
    scan_row<Ev, CAPN, 8>(linc + (size_t)w * Ev, g_nedges + (size_t)w * CAPN, g_ncnt + w, lane);
}

// ---------------- K3: warp-per-edge register gather (x stays in L2) -----------
__global__ void k3_gather(const float* __restrict__ x) {
    int e = (blockIdx.x * blockDim.x + threadIdx.x) >> 5;   // 16384 warps
    int lane = threadIdx.x & 31;

    int cnt = g_ecnt[e];
    const int* nl = g_enodes + (size_t)e * CAPE;
    int myn0 = (lane < cnt) ? nl[lane] : 0;
    int myn1 = (32 + lane < cnt) ? nl[32 + lane] : 0;

    const int boff = (lane >> 2) * (Nv * Cv / 4) + (lane & 3);

    float4 acc[8];
#pragma unroll
    for (int q = 0; q < 8; ++q) acc[q] = make_float4(0.f, 0.f, 0.f, 0.f);

    const float4* x4 = (const float4*)x;
    for (int i = 0; i < cnt; ++i) {
        int n = (i < 32) ? __shfl_sync(0xffffffffu, myn0, i)
                         : __shfl_sync(0xffffffffu, myn1, i - 32);
        const float4* xn = x4 + (size_t)n * (Cv / 4) + boff;
#pragma unroll
        for (int q = 0; q < 8; ++q) {
            float4 v = xn[(size_t)q * 8 * (Nv * Cv / 4)];
            acc[q].x += v.x; acc[q].y += v.y; acc[q].z += v.z; acc[q].w += v.w;
        }
    }

    float4* zw = (float4*)(g_z + (size_t)e * (Bv * Cv));
#pragma unroll
    for (int q = 0; q < 8; ++q) zw[q * 32 + lane] = acc[q];
}

// ---------------- K4a: stage 1 only, y -> gmem ----------------
// grid: 2048 (one per node), block 256, smem ~7KB -> 3+ CTAs/SM
__global__ void __launch_bounds__(256, 3) k4a_stage1() {
    __shared__ float w_s[CAPN * 8];
    __shared__ int   el_s[CAPNP];

    int n = blockIdx.x, t = threadIdx.x;
    int cnt = g_ncnt[n];
    if (t < CAPNP) el_s[t] = (t < cnt) ? g_nedges[(size_t)n * CAPN + t] : 0;
    if (t < CAPN) {
        if (t < cnt) {
            int e = el_s[t];
            *(float4*)(w_s + t * 8)     = *(const float4*)(g_w + (size_t)e * 8);
            *(float4*)(w_s + t * 8 + 4) = *(const float4*)(g_w + (size_t)e * 8 + 4);
        } else {
            *(float4*)(w_s + t * 8)     = make_float4(0.f, 0.f, 0.f, 0.f);
            *(float4*)(w_s + t * 8 + 4) = make_float4(0.f, 0.f, 0.f, 0.f);
        }
    }
    __syncthreads();

    int b = t >> 2, cq = t & 3;
    const size_t zoff = (size_t)b * Cv + cq * 4;
    u64 acc[4][4];
#pragma unroll
    for (int ci = 0; ci < 4; ++ci)
#pragma unroll
        for (int kq = 0; kq < 4; ++kq) acc[ci][kq] = 0ull;

    const u64* w_s2 = (const u64*)w_s;
    int cnt4 = (cnt + 3) & ~3;

    float4 pz[4];
#pragma unroll
    for (int u = 0; u < 4; ++u)
        pz[u] = *(const float4*)(g_z + (size_t)el_s[u] * (Bv * Cv) + zoff);

    for (int i = 0; i < cnt4; i += 4) {
#pragma unroll
        for (int u = 0; u < 4; ++u) {
            float4 zv = pz[u];
            pz[u] = *(const float4*)(g_z + (size_t)el_s[i + 4 + u] * (Bv * Cv) + zoff);
            u64 z0 = pack2(zv.x, zv.x), z1 = pack2(zv.y, zv.y);
            u64 z2 = pack2(zv.z, zv.z), z3 = pack2(zv.w, zv.w);
            u64 w0 = w_s2[(i + u) * 4 + 0], w1 = w_s2[(i + u) * 4 + 1];
            u64 w2 = w_s2[(i + u) * 4 + 2], w3 = w_s2[(i + u) * 4 + 3];
            ffma2(acc[0][0], z0, w0); ffma2(acc[0][1], z0, w1); ffma2(acc[0][2], z0, w2); ffma2(acc[0][3], z0, w3);
            ffma2(acc[1][0], z1, w0); ffma2(acc[1][1], z1, w1); ffma2(acc[1][2], z1, w2); ffma2(acc[1][3], z1, w3);
            ffma2(acc[2][0], z2, w0); ffma2(acc[2][1], z2, w1); ffma2(acc[2][2], z2, w2); ffma2(acc[2][3], z2, w3);
            ffma2(acc[3][0], z3, w0); ffma2(acc[3][1], z3, w1); ffma2(acc[3][2], z3, w2); ffma2(acc[3][3], z3, w3);
        }
    }

    // store y pairs: row (n,b), u64 col j = (cq*4+ci)*4+kq
    u64* yrow = g_y + ((size_t)n << 12) + (size_t)b * 64;
#pragma unroll
    for (int ci = 0; ci < 4; ++ci) {
        int j0 = (cq * 4 + ci) * 4;
        *(ulonglong2*)(yrow + j0)     = make_ulonglong2(acc[ci][0], acc[ci][1]);
        *(ulonglong2*)(yrow + j0 + 2) = make_ulonglong2(acc[ci][2], acc[ci][3]);
    }
}

// ---------------- K4b: GEMM out[b][g] = relu(y[b]·gcw[g] + gcb[g]) -----------
// grid: 2048 (one per node), block 256, dyn smem 64KB -> 3 CTAs/SM
__global__ void __launch_bounds__(256, 3) k4b_gemm(const float* __restrict__ gcw,
                                                   const float* __restrict__ gcb,
                                                   float* __restrict__ out) {
    extern __shared__ char smem[];
    float* gcw_s = (float*)smem;            // 32KB
    u64*   y_s   = (u64*)(smem + 32768);    // 32KB, xor-swizzled

    int n = blockIdx.x, t = threadIdx.x;

    for (int i = t; i < (Gv * CKv) / 4; i += 256)
        ((float4*)gcw_s)[i] = ((const float4*)gcw)[i];

    // load y tile (coalesced 16B) and write swizzled
    const ulonglong2* ysrc = (const ulonglong2*)(g_y + ((size_t)n << 12));
#pragma unroll
    for (int q = 0; q < 8; ++q) {
        int m = t * 8 + q;                  // ulonglong2 index 0..2047
        ulonglong2 v = ysrc[m];
        int u0 = 2 * m;                     // u64 flat index
        int b = u0 >> 6, j = u0 & 63;       // j even
        int bs = b >> 2;
        int p = j ^ bs;                     // slots {p, p^1}
        u64* row = y_s + b * 64;
        row[p] = v.x; row[p ^ 1] = v.y;
    }
    __syncthreads();

    int bq = t & 15, gq = t >> 4;
    u64 a2[4][4];
#pragma unroll
    for (int ib = 0; ib < 4; ++ib)
#pragma unroll
        for (int ig = 0; ig < 4; ++ig) a2[ib][ig] = 0ull;

#pragma unroll 4
    for (int j = 0; j < 64; ++j) {
        int js = j ^ bq;
        u64 y0 = y_s[(bq * 4 + 0) * 64 + js];
        u64 y1 = y_s[(bq * 4 + 1) * 64 + js];
        u64 y2 = y_s[(bq * 4 + 2) * 64 + js];
        u64 y3 = y_s[(bq * 4 + 3) * 64 + js];
        u64 g0 = *(const u64*)(gcw_s + (gq * 4 + 0) * CKv + 2 * j);
        u64 g1 = *(const u64*)(gcw_s + (gq * 4 + 1) * CKv + 2 * j);
        u64 g2 = *(const u64*)(gcw_s + (gq * 4 + 2) * CKv + 2 * j);
        u64 g3 = *(const u64*)(gcw_s + (gq * 4 + 3) * CKv + 2 * j);
        ffma2(a2[0][0], y0, g0); ffma2(a2[0][1], y0, g1); ffma2(a2[0][2], y0, g2); ffma2(a2[0][3], y0, g3);
        ffma2(a2[1][0], y1, g0); ffma2(a2[1][1], y1, g1); ffma2(a2[1][2], y1, g2); ffma2(a2[1][3], y1, g3);
        ffma2(a2[2][0], y2, g0); ffma2(a2[2][1], y2, g1); ffma2(a2[2][2], y2, g2); ffma2(a2[2][3], y2, g3);
        ffma2(a2[3][0], y3, g0); ffma2(a2[3][1], y3, g1); ffma2(a2[3][2], y3, g2); ffma2(a2[3][3], y3, g3);
    }

    float4 cb = *(const float4*)(gcb + gq * 4);
#pragma unroll
    for (int ib = 0; ib < 4; ++ib) {
        int bb = bq * 4 + ib;
        float4 o;
        o.x = fmaxf(hsum2(a2[ib][0]) + cb.x, 0.0f);
        o.y = fmaxf(hsum2(a2[ib][1]) + cb.y, 0.0f);
        o.z = fmaxf(hsum2(a2[ib][2]) + cb.z, 0.0f);
        o.w = fmaxf(hsum2(a2[ib][3]) + cb.w, 0.0f);
        *(float4*)(out + (size_t)bb * NGv + n * Gv + gq * 4) = o;
    }
}

// ---------------- launcher ----------------
extern "C" void kernel_launch(void* const* d_in, const int* in_sizes, int n_in,
                              void* d_out, int out_size) {
    const float* x    = (const float*)d_in[0];
    const float* linc = (const float*)d_in[1];
    const float* rinc = (const float*)d_in[2];
    const float* ef   = (const float*)d_in[3];
    const float* w1   = (const float*)d_in[4];
    const float* b1   = (const float*)d_in[5];
    const float* w2   = (const float*)d_in[6];
    const float* b2   = (const float*)d_in[7];
    const float* gcw  = (const float*)d_in[8];
    const float* gcb  = (const float*)d_in[9];
    float* out = (float*)d_out;

    (void)in_sizes; (void)n_in; (void)out_size;

    cudaFuncSetAttribute(k4b_gemm, cudaFuncAttributeMaxDynamicSharedMemorySize, 65536);

    k0_edgew<<<Ev / 128, 128>>>(ef, w1, b1, w2, b2);
    k1_scan_rinc<<<Ev / 8, 256>>>(rinc);       // warp per edge row
    k2_scan_linc<<<Nv / 8, 256>>>(linc);       // warp per node row, MLP 8
    k3_gather<<<Ev / 8, 256>>>(x);             // warp per edge
    k4a_stage1<<<Nv, 256>>>();
    k4b_gemm<<<Nv, 256, 65536>>>(gcw, gcb, out);
}

// round 6
// speedup vs baseline: 1.1070x; 1.1070x over previous
#include <cuda_runtime.h>
#include <cstddef>

// Problem constants
#define Bv 64
#define Nv 2048
#define Ev 16384
#define Fv 32
#define Hv 64
#define Kv 8
#define Cv 16
#define Gv 64
#define CKv 128          // C*K
#define NGv 131072       // N*G
#define CAPE 64          // max nodes per edge (mean 8)
#define CAPN 192         // max edges per node (mean 64)
#define CAPNP (CAPN + 8) // padded edge list (prefetch overrun guard)

typedef unsigned long long u64;

__device__ __forceinline__ u64 pack2(float lo, float hi) {
    u64 r; asm("mov.b64 %0,{%1,%2};" : "=l"(r) : "f"(lo), "f"(hi)); return r;
}
__device__ __forceinline__ void ffma2(u64& d, u64 a, u64 b) {
    asm("fma.rn.f32x2 %0,%1,%2,%0;" : "+l"(d) : "l"(a), "l"(b));
}
__device__ __forceinline__ float hsum2(u64 v) {
    float lo, hi; asm("mov.b64 {%0,%1},%2;" : "=f"(lo), "=f"(hi) : "l"(v));
    return lo + hi;
}

// ---------------- scratch (device globals; no allocation) ----------------
__device__ float g_w[Ev * Kv];                 // per-edge kernel weights [E,K]
__device__ int   g_ecnt[Ev];
__device__ int   g_enodes[Ev * CAPE];          // rinc CSR: nodes per edge
__device__ int   g_ncnt[Nv];
__device__ int   g_nedges[Nv * CAPN];          // linc CSR: edges per node
__device__ float g_z[(size_t)Ev * Bv * Cv];    // z in (E,B,C) layout, 67MB

// ---------------- K0: edge MLP -> w[E,K] ----------------
__global__ void k0_edgew(const float* __restrict__ ef,
                         const float* __restrict__ w1, const float* __restrict__ b1,
                         const float* __restrict__ w2, const float* __restrict__ b2) {
    __shared__ float w1s[Hv * Fv];
    __shared__ float w2s[Kv * Hv];
    __shared__ float b1s[Hv];
    __shared__ float b2s[Kv];
    int t = threadIdx.x;
    for (int i = t; i < Hv * Fv; i += 128) w1s[i] = w1[i];
    for (int i = t; i < Kv * Hv; i += 128) w2s[i] = w2[i];
    if (t < Hv) b1s[t] = b1[t];
    if (t < Kv) b2s[t] = b2[t];
    __syncthreads();

    int e = blockIdx.x * 128 + t;
    float efr[Fv];
#pragma unroll
    for (int q = 0; q < Fv / 4; ++q)
        ((float4*)efr)[q] = ((const float4*)(ef + (size_t)e * Fv))[q];
    float wk[Kv];
#pragma unroll
    for (int k = 0; k < Kv; ++k) wk[k] = b2s[k];
    for (int j = 0; j < Hv; ++j) {
        float s = b1s[j];
#pragma unroll
        for (int f = 0; f < Fv; ++f) s += efr[f] * w1s[j * Fv + f];
        s = fmaxf(s, 0.0f);
#pragma unroll
        for (int k = 0; k < Kv; ++k) wk[k] += s * w2s[k * Hv + j];
    }
#pragma unroll
    for (int k = 0; k < Kv; ++k) g_w[e * Kv + k] = wk[k];
}

// ---------------- ordered sparse row scan (deterministic compaction) ---------
template <int COLS, int CAP, int UNROLL>
__device__ __forceinline__ void scan_row(const float* __restrict__ row,
                                         int* __restrict__ outp,
                                         int* __restrict__ cntp, int lane) {
    int cnt = 0;
    const float4* r4 = (const float4*)row;
    const unsigned lt = (1u << lane) - 1u;
    for (int g = 0; g < COLS / 128; g += UNROLL) {
        float4 v[UNROLL];
#pragma unroll
        for (int u = 0; u < UNROLL; ++u) v[u] = r4[(size_t)(g + u) * 32 + lane];
#pragma unroll
        for (int u = 0; u < UNROLL; ++u) {
            float a0 = v[u].x, a1 = v[u].y, a2 = v[u].z, a3 = v[u].w;
            unsigned m0 = __ballot_sync(0xffffffffu, a0 != 0.0f);
            unsigned m1 = __ballot_sync(0xffffffffu, a1 != 0.0f);
            unsigned m2 = __ballot_sync(0xffffffffu, a2 != 0.0f);
            unsigned m3 = __ballot_sync(0xffffffffu, a3 != 0.0f);
            int prefix = __popc(m0 & lt) + __popc(m1 & lt) + __popc(m2 & lt) + __popc(m3 & lt);
            int base = (g + u) * 128 + lane * 4;
            int own = 0;
            if (a0 != 0.0f) { int p = cnt + prefix + own; if (p < CAP) outp[p] = base + 0; own++; }
            if (a1 != 0.0f) { int p = cnt + prefix + own; if (p < CAP) outp[p] = base + 1; own++; }
            if (a2 != 0.0f) { int p = cnt + prefix + own; if (p < CAP) outp[p] = base + 2; own++; }
            if (a3 != 0.0f) { int p = cnt + prefix + own; if (p < CAP) outp[p] = base + 3; own++; }
            cnt += __popc(m0) + __popc(m1) + __popc(m2) + __popc(m3);
        }
    }
    if (lane == 0) *cntp = (cnt < CAP) ? cnt : CAP;
}

// K1: rinc (E,N) -> per-edge node lists
__global__ void k1_scan_rinc(const float* __restrict__ rinc) {
    int w = (blockIdx.x * blockDim.x + threadIdx.x) >> 5;
    int lane = threadIdx.x & 31;
    scan_row<Nv, CAPE, 4>(rinc + (size_t)w * Nv, g_enodes + (size_t)w * CAPE, g_ecnt + w, lane);
}

// K2: linc (N,E) -> per-node edge lists (UNROLL 8 -> MLP 8; only 2048 warps)
__global__ void k2_scan_linc(const float* __restrict__ linc) {
    int w = (blockIdx.x * blockDim.x + threadIdx.x) >> 5;
    int lane = threadIdx.x & 31;
    scan_row<Ev, CAPN, 8>(linc + (size_t)w * Ev, g_nedges + (size_t)w * CAPN, g_ncnt + w, lane);
}

// ---------------- K3: warp-per-edge register gather (x stays in L2) -----------
__global__ void k3_gather(const float* __restrict__ x) {
    int e = (blockIdx.x * blockDim.x + threadIdx.x) >> 5;   // 16384 warps
    int lane = threadIdx.x & 31;

    int cnt = g_ecnt[e];
    const int* nl = g_enodes + (size_t)e * CAPE;
    int myn0 = (lane < cnt) ? nl[lane] : 0;
    int myn1 = (32 + lane < cnt) ? nl[32 + lane] : 0;

    const int boff = (lane >> 2) * (Nv * Cv / 4) + (lane & 3);

    float4 acc[8];
#pragma unroll
    for (int q = 0; q < 8; ++q) acc[q] = make_float4(0.f, 0.f, 0.f, 0.f);

    const float4* x4 = (const float4*)x;
    for (int i = 0; i < cnt; ++i) {
        int n = (i < 32) ? __shfl_sync(0xffffffffu, myn0, i)
                         : __shfl_sync(0xffffffffu, myn1, i - 32);
        const float4* xn = x4 + (size_t)n * (Cv / 4) + boff;
#pragma unroll
        for (int q = 0; q < 8; ++q) {
            float4 v = xn[(size_t)q * 8 * (Nv * Cv / 4)];
            acc[q].x += v.x; acc[q].y += v.y; acc[q].z += v.z; acc[q].w += v.w;
        }
    }

    float4* zw = (float4*)(g_z + (size_t)e * (Bv * Cv));
#pragma unroll
    for (int q = 0; q < 8; ++q) zw[q * 32 + lane] = acc[q];
}

// ---------------- K4: fused per-node y + GEMM + relu ----------------
// grid: 2048 (one per node), block 256, dyn smem 72480, 3 CTAs/SM forced
__global__ void __launch_bounds__(256, 3) k4_main(const float* __restrict__ gcw,
                                                  const float* __restrict__ gcb,
                                                  float* __restrict__ out) {
    extern __shared__ char smem[];
    float* gcw_s = (float*)smem;                        // 64*128 floats = 32KB
    u64*   y_s   = (u64*)(smem + 32768);                // 64*64 u64 = 32KB (xor-swizzled)
    float* w_s   = (float*)(smem + 65536);              // CAPN*8 = 6144B (zero-padded)
    int*   el_s  = (int*)(smem + 65536 + CAPN * 8 * 4); // CAPNP ints (zero-padded)

    int n = blockIdx.x, t = threadIdx.x;

    for (int i = t; i < (Gv * CKv) / 4; i += 256)
        ((float4*)gcw_s)[i] = ((const float4*)gcw)[i];
    int cnt = g_ncnt[n];
    // padded edge list: entries >= cnt point at edge 0 with zero weights
    if (t < CAPNP) el_s[t] = (t < cnt) ? g_nedges[(size_t)n * CAPN + t] : 0;
    if (t < CAPN) {
        if (t < cnt) {
            int e = el_s[t];
            *(float4*)(w_s + t * 8)     = *(const float4*)(g_w + (size_t)e * 8);
            *(float4*)(w_s + t * 8 + 4) = *(const float4*)(g_w + (size_t)e * 8 + 4);
        } else {
            *(float4*)(w_s + t * 8)     = make_float4(0.f, 0.f, 0.f, 0.f);
            *(float4*)(w_s + t * 8 + 4) = make_float4(0.f, 0.f, 0.f, 0.f);
        }
    }
    __syncthreads();

    // ---- stage 1: y[b][ck] = sum_e w[e][k] * z[e][b][c], depth-4 pipeline ----
    int b = t >> 2, cq = t & 3;
    const size_t zoff = (size_t)b * Cv + cq * 4;   // within z[e] tile
    u64 acc[4][4];
#pragma unroll
    for (int ci = 0; ci < 4; ++ci)
#pragma unroll
        for (int kq = 0; kq < 4; ++kq) acc[ci][kq] = 0ull;

    const u64* w_s2 = (const u64*)w_s;
    int cnt4 = (cnt + 3) & ~3;                     // padded iterations are exact zeros

    float4 pz[4];
#pragma unroll
    for (int u = 0; u < 4; ++u)
        pz[u] = *(const float4*)(g_z + (size_t)el_s[u] * (Bv * Cv) + zoff);

    for (int i = 0; i < cnt4; i += 4) {
#pragma unroll
        for (int u = 0; u < 4; ++u) {
            float4 zv = pz[u];
            pz[u] = *(const float4*)(g_z + (size_t)el_s[i + 4 + u] * (Bv * Cv) + zoff);
            u64 z0 = pack2(zv.x, zv.x), z1 = pack2(zv.y, zv.y);
            u64 z2 = pack2(zv.z, zv.z), z3 = pack2(zv.w, zv.w);
            u64 w0 = w_s2[(i + u) * 4 + 0], w1 = w_s2[(i + u) * 4 + 1];
            u64 w2 = w_s2[(i + u) * 4 + 2], w3 = w_s2[(i + u) * 4 + 3];
            ffma2(acc[0][0], z0, w0); ffma2(acc[0][1], z0, w1); ffma2(acc[0][2], z0, w2); ffma2(acc[0][3], z0, w3);
            ffma2(acc[1][0], z1, w0); ffma2(acc[1][1], z1, w1); ffma2(acc[1][2], z1, w2); ffma2(acc[1][3], z1, w3);
            ffma2(acc[2][0], z2, w0); ffma2(acc[2][1], z2, w1); ffma2(acc[2][2], z2, w2); ffma2(acc[2][3], z2, w3);
            ffma2(acc[3][0], z3, w0); ffma2(acc[3][1], z3, w1); ffma2(acc[3][2], z3, w2); ffma2(acc[3][3], z3, w3);
        }
    }

    int bs = b >> 2;
#pragma unroll
    for (int ci = 0; ci < 4; ++ci)
#pragma unroll
        for (int kq = 0; kq < 4; ++kq) {
            int j = (cq * 4 + ci) * 4 + kq;            // pair index over ck
            y_s[b * 64 + (j ^ bs)] = acc[ci][kq];
        }
    __syncthreads();

    // ---- stage 2: out[b][g] = relu(sum_ck y[b][ck]*gcw[g][ck] + gcb[g]) ----
    int bq = t & 15, gq = t >> 4;
    u64 a2[4][4];
#pragma unroll
    for (int ib = 0; ib < 4; ++ib)
#pragma unroll
        for (int ig = 0; ig < 4; ++ig) a2[ib][ig] = 0ull;

#pragma unroll 4
    for (int j = 0; j < 64; ++j) {
        int js = j ^ bq;
        u64 y0 = y_s[(bq * 4 + 0) * 64 + js];
        u64 y1 = y_s[(bq * 4 + 1) * 64 + js];
        u64 y2 = y_s[(bq * 4 + 2) * 64 + js];
        u64 y3 = y_s[(bq * 4 + 3) * 64 + js];
        u64 g0 = *(const u64*)(gcw_s + (gq * 4 + 0) * CKv + 2 * j);
        u64 g1 = *(const u64*)(gcw_s + (gq * 4 + 1) * CKv + 2 * j);
        u64 g2 = *(const u64*)(gcw_s + (gq * 4 + 2) * CKv + 2 * j);
        u64 g3 = *(const u64*)(gcw_s + (gq * 4 + 3) * CKv + 2 * j);
        ffma2(a2[0][0], y0, g0); ffma2(a2[0][1], y0, g1); ffma2(a2[0][2], y0, g2); ffma2(a2[0][3], y0, g3);
        ffma2(a2[1][0], y1, g0); ffma2(a2[1][1], y1, g1); ffma2(a2[1][2], y1, g2); ffma2(a2[1][3], y1, g3);
        ffma2(a2[2][0], y2, g0); ffma2(a2[2][1], y2, g1); ffma2(a2[2][2], y2, g2); ffma2(a2[2][3], y2, g3);
        ffma2(a2[3][0], y3, g0); ffma2(a2[3][1], y3, g1); ffma2(a2[3][2], y3, g2); ffma2(a2[3][3], y3, g3);
    }

    float4 cb = *(const float4*)(gcb + gq * 4);
#pragma unroll
    for (int ib = 0; ib < 4; ++ib) {
        int bb = bq * 4 + ib;
        float4 o;
        o.x = fmaxf(hsum2(a2[ib][0]) + cb.x, 0.0f);
        o.y = fmaxf(hsum2(a2[ib][1]) + cb.y, 0.0f);
        o.z = fmaxf(hsum2(a2[ib][2]) + cb.z, 0.0f);
        o.w = fmaxf(hsum2(a2[ib][3]) + cb.w, 0.0f);
        *(float4*)(out + (size_t)bb * NGv + n * Gv + gq * 4) = o;
    }
}

// ---------------- launcher ----------------
extern "C" void kernel_launch(void* const* d_in, const int* in_sizes, int n_in,
                              void* d_out, int out_size) {
    const float* x    = (const float*)d_in[0];
    const float* linc = (const float*)d_in[1];
    const float* rinc = (const float*)d_in[2];
    const float* ef   = (const float*)d_in[3];
    const float* w1   = (const float*)d_in[4];
    const float* b1   = (const float*)d_in[5];
    const float* w2   = (const float*)d_in[6];
    const float* b2   = (const float*)d_in[7];
    const float* gcw  = (const float*)d_in[8];
    const float* gcb  = (const float*)d_in[9];
    float* out = (float*)d_out;

    (void)in_sizes; (void)n_in; (void)out_size;

    const int SMEM4 = 65536 + CAPN * 8 * 4 + CAPNP * 4;  // 72480
    cudaFuncSetAttribute(k4_main, cudaFuncAttributeMaxDynamicSharedMemorySize, SMEM4);

    k0_edgew<<<Ev / 128, 128>>>(ef, w1, b1, w2, b2);
    k1_scan_rinc<<<Ev / 8, 256>>>(rinc);       // warp per edge row
    k2_scan_linc<<<Nv / 8, 256>>>(linc);       // warp per node row, MLP 8
    k3_gather<<<Ev / 8, 256>>>(x);             // warp per edge
    k4_main<<<Nv, 256, SMEM4>>>(gcw, gcb, out);
}